// round 12
// baseline (speedup 1.0000x reference)
#include <cuda_runtime.h>
#include <cuda_fp16.h>
#include <math.h>
#include <stdint.h>

#define EDIM 4096
#define NH   32
#define HD   128
#define Lseq 8192
#define Bb   2
#define VD   1536
#define NQ   64
#define NROWS (Bb*Lseq)

// ---------------- scratch ----------------
__device__ float  g_kvraw[NROWS * EDIM];
__device__ __half g_hcube[NROWS * VD];
__device__ __half g_hw[EDIM * VD];
__device__ __half g_hkv[NROWS * EDIM];
__device__ __half g_hrot[NROWS * EDIM];
__device__ __half g_hkvT[(size_t)Bb * EDIM * Lseq];
__device__ float  g_scores[(size_t)Bb * 2048 * Lseq];
__device__ __half g_hattn[(size_t)Bb * 2048 * Lseq];
__device__ float  g_qn[NQ * EDIM];
__device__ float  g_qp[NQ * EDIM];
__device__ float  g_qk[2048 * EDIM];
__device__ __half g_hqk[2048 * EDIM];
__device__ float  g_U[(size_t)Bb * 2048 * EDIM];
__device__ float  g_ctx[128 * EDIM];
__device__ float  g_out1[128 * EDIM];
__device__ float  g_ln2[128 * EDIM];
__device__ float  g_WkT[(size_t)EDIM * EDIM];
__device__ float  g_projT[(size_t)EDIM * EDIM];
__device__ float  g_bc[EDIM];

// ---------------- asm helpers ----------------
__device__ __forceinline__ void mma_f16(float c[4], uint32_t a0, uint32_t a1,
                                        uint32_t a2, uint32_t a3,
                                        uint32_t b0, uint32_t b1) {
    asm("mma.sync.aligned.m16n8k16.row.col.f32.f16.f16.f32 "
        "{%0,%1,%2,%3}, {%4,%5,%6,%7}, {%8,%9}, {%0,%1,%2,%3};"
        : "+f"(c[0]), "+f"(c[1]), "+f"(c[2]), "+f"(c[3])
        : "r"(a0), "r"(a1), "r"(a2), "r"(a3), "r"(b0), "r"(b1));
}
__device__ __forceinline__ void ldsm4(uint32_t& r0, uint32_t& r1, uint32_t& r2,
                                      uint32_t& r3, uint32_t a) {
    asm volatile("ldmatrix.sync.aligned.m8n8.x4.shared.b16 {%0,%1,%2,%3}, [%4];"
                 : "=r"(r0), "=r"(r1), "=r"(r2), "=r"(r3) : "r"(a));
}
__device__ __forceinline__ void cp16(uint32_t s, const void* g) {
    asm volatile("cp.async.cg.shared.global [%0], [%1], 16;" :: "r"(s), "l"(g));
}
#define CP_COMMIT() asm volatile("cp.async.commit_group;")
#define CP_WAIT1()  asm volatile("cp.async.wait_group 1;" ::: "memory")
#define CP_WAIT0()  asm volatile("cp.async.wait_group 0;" ::: "memory")

// ---------------- fp16 TN GEMM: C(fp32) = alpha*(A . B^T) ----------------
// Block 128x256, 8 warps 64x64. M%128==0, N%256==0, K%32==0.
// 3-stage cp.async pipeline (wait_group 1), ldmatrix fragments.
#define STAGEB 30720               // (128 + 256) rows * 80 B
#define GSMB  (3 * STAGEB)         // 92160 B
__global__ __launch_bounds__(256, 1)
void gemm_h(const __half* __restrict__ A, int lda, size_t sAz,
            const __half* __restrict__ B, int ldb, size_t sBz,
            float* __restrict__ C, int ldc, size_t sCz,
            int K, float alpha) {
    extern __shared__ __align__(16) uint32_t sm[];
    uint32_t smB = (uint32_t)__cvta_generic_to_shared(sm);
    int t = threadIdx.x, lane = t & 31, wid = t >> 5;
    A += (size_t)blockIdx.z * sAz;
    B += (size_t)blockIdx.z * sBz;
    C += (size_t)blockIdx.z * sCz;
    int m0 = blockIdx.y * 128, n0 = blockIdx.x * 256;
    int wm = (wid & 1) * 64, wn = (wid >> 1) * 64;
    int lr = lane >> 2, lc = lane & 3;

    // staging: A row ar (2 x 16B by 2 threads), B row t (4 x 16B); row stride 80 B
    int ar = t >> 1, ah = t & 1;
    const __half* gA = A + (size_t)(m0 + ar) * lda + ah * 16;
    const __half* gB = B + (size_t)(n0 + t) * ldb;
    uint32_t sAoff = ar * 80 + ah * 32;
    uint32_t sBoff = 10240 + t * 80;

    // fragment base offsets (bytes, within a stage)
    uint32_t aBase = (wm + (lane & 15)) * 80 + ((lane >> 4) & 1) * 16;
    uint32_t bBase = 10240 + (wn + (lane & 7) + ((lane >> 4) & 1) * 8) * 80 +
                     ((lane >> 3) & 1) * 16;

    float acc[4][8][4];
#pragma unroll
    for (int i = 0; i < 4; i++)
#pragma unroll
        for (int j = 0; j < 8; j++)
#pragma unroll
            for (int v = 0; v < 4; v++) acc[i][j][v] = 0.f;

    int S = K >> 5;  // stages of K=32
    // prologue: stages 0, 1
#pragma unroll
    for (int p = 0; p < 2; p++) {
        uint32_t base = smB + p * STAGEB;
        const __half* qA = gA + p * 32;
        const __half* qB = gB + p * 32;
        cp16(base + sAoff, qA); cp16(base + sAoff + 16, qA + 8);
#pragma unroll
        for (int c = 0; c < 4; c++) cp16(base + sBoff + c * 16, qB + c * 8);
        CP_COMMIT();
    }

    int buf = 0;
    for (int s = 0; s < S; s++) {
        CP_WAIT1();
        __syncthreads();
        if (s + 2 < S) {
            int nb = buf + 2; if (nb >= 3) nb -= 3;
            uint32_t base = smB + nb * STAGEB;
            const __half* qA = gA + (s + 2) * 32;
            const __half* qB = gB + (s + 2) * 32;
            cp16(base + sAoff, qA); cp16(base + sAoff + 16, qA + 8);
#pragma unroll
            for (int c = 0; c < 4; c++) cp16(base + sBoff + c * 16, qB + c * 8);
            CP_COMMIT();
        }
        uint32_t sa = smB + buf * STAGEB + aBase;
        uint32_t sb = smB + buf * STAGEB + bBase;
#pragma unroll
        for (int kk = 0; kk < 2; kk++) {
            uint32_t af[4][4], bf[8][2];
#pragma unroll
            for (int i = 0; i < 4; i++)
                ldsm4(af[i][0], af[i][1], af[i][2], af[i][3],
                      sa + i * 1280 + kk * 32);
#pragma unroll
            for (int jp = 0; jp < 4; jp++)
                ldsm4(bf[2 * jp][0], bf[2 * jp][1], bf[2 * jp + 1][0],
                      bf[2 * jp + 1][1], sb + jp * 1280 + kk * 32);
#pragma unroll
            for (int i = 0; i < 4; i++)
#pragma unroll
                for (int j = 0; j < 8; j++)
                    mma_f16(acc[i][j], af[i][0], af[i][1], af[i][2], af[i][3],
                            bf[j][0], bf[j][1]);
        }
        __syncthreads();
        buf++; if (buf == 3) buf = 0;
    }

#pragma unroll
    for (int i = 0; i < 4; i++) {
        int row = m0 + wm + i * 16 + lr;
#pragma unroll
        for (int j = 0; j < 8; j++) {
            int col = n0 + wn + j * 8 + lc * 2;
            *(float2*)&C[(size_t)row * ldc + col] =
                make_float2(acc[i][j][0] * alpha, acc[i][j][1] * alpha);
            *(float2*)&C[(size_t)(row + 8) * ldc + col] =
                make_float2(acc[i][j][2] * alpha, acc[i][j][3] * alpha);
        }
    }
}

// ---------------- fp32 split-K GEMM (small), atomic accumulate ----------------
__device__ __forceinline__
void sg_body(const float* __restrict__ A, int lda,
             const float* __restrict__ B, int ldb,
             float* __restrict__ C, int ldc, int n0, int Ks) {
    __shared__ float As[8][64], Bs[8][64];
    int t = threadIdx.x;
    int row = t & 63, kc = t >> 6;
    int ty = t >> 4, tx = t & 15;
    float acc[4][4];
#pragma unroll
    for (int i = 0; i < 4; i++)
#pragma unroll
        for (int j = 0; j < 4; j++) acc[i][j] = 0.f;
    for (int k0 = 0; k0 < Ks; k0 += 8) {
        float2 a = *(const float2*)&A[(size_t)row * lda + k0 + kc * 2];
        float2 b = *(const float2*)&B[(size_t)(n0 + row) * ldb + k0 + kc * 2];
        As[kc * 2][row] = a.x; As[kc * 2 + 1][row] = a.y;
        Bs[kc * 2][row] = b.x; Bs[kc * 2 + 1][row] = b.y;
        __syncthreads();
#pragma unroll
        for (int k = 0; k < 8; k++) {
            float av[4] = {As[k][ty * 4], As[k][ty * 4 + 1],
                           As[k][ty * 4 + 2], As[k][ty * 4 + 3]};
            float bv[4] = {Bs[k][tx * 4], Bs[k][tx * 4 + 1],
                           Bs[k][tx * 4 + 2], Bs[k][tx * 4 + 3]};
#pragma unroll
            for (int i = 0; i < 4; i++)
#pragma unroll
                for (int j = 0; j < 4; j++)
                    acc[i][j] = fmaf(av[i], bv[j], acc[i][j]);
        }
        __syncthreads();
    }
#pragma unroll
    for (int i = 0; i < 4; i++)
#pragma unroll
        for (int j = 0; j < 4; j++)
            atomicAdd(&C[(size_t)(ty * 4 + i) * ldc + n0 + tx * 4 + j], acc[i][j]);
}

__global__ __launch_bounds__(256)
void sg_lin(const float* A, int lda, const float* B, int ldb,
            float* C, int ldc, int Ks) {
    sg_body(A + (size_t)blockIdx.y * 64 * lda + (size_t)blockIdx.z * Ks, lda,
            B + (size_t)blockIdx.z * Ks, ldb,
            C + (size_t)blockIdx.y * 64 * ldc, ldc, blockIdx.x * 64, Ks);
}
__global__ __launch_bounds__(256)
void sg_qk(const float* qp, const float* WkT, float* qk) {
    int h = blockIdx.z;
    sg_body(qp + h * 128, EDIM, WkT + h * 128, EDIM,
            qk + (size_t)h * 64 * EDIM, EDIM, blockIdx.x * 64, 128);
}
__global__ __launch_bounds__(256)
void sg_vproj(const float* U, const float* Wv, float* ctx) {
    int z = blockIdx.z;
    int bh = z >> 2, s = z & 3;
    int b = bh >> 5, h = bh & 31;
    sg_body(U + (size_t)bh * 64 * EDIM + s * 1024, EDIM,
            Wv + (size_t)h * 128 * EDIM + s * 1024, EDIM,
            ctx + (size_t)b * 64 * EDIM + h * 128, EDIM, blockIdx.x * 64, 1024);
}

__global__ void init_rows(float* C, const float* bias, int ld) {
    int f = blockIdx.x * 256 + threadIdx.x;
    C[(size_t)blockIdx.y * ld + f] = bias ? bias[f] : 0.f;
}

// ---------------- elementwise / misc ----------------
__global__ void cvt_h(const float* __restrict__ in, __half* __restrict__ out, int n4) {
    int i = blockIdx.x * blockDim.x + threadIdx.x;
    if (i < n4) {
        float4 v = ((const float4*)in)[i];
        ((__half2*)out)[i * 2]     = __floats2half2_rn(v.x, v.y);
        ((__half2*)out)[i * 2 + 1] = __floats2half2_rn(v.z, v.w);
    }
}

__global__ void transpose_hh(const __half* __restrict__ in, __half* __restrict__ out,
                             int R, int Cc, size_t sIn, size_t sOut) {
    __shared__ __half tile[32][33];
    in += (size_t)blockIdx.z * sIn;
    out += (size_t)blockIdx.z * sOut;
    int r0 = blockIdx.x * 32, c0 = blockIdx.y * 32;
    int x = threadIdx.x, y = threadIdx.y;
    for (int i = y; i < 32; i += 8)
        tile[i][x] = in[(size_t)(r0 + i) * Cc + c0 + x];
    __syncthreads();
    for (int i = y; i < 32; i += 8)
        out[(size_t)(c0 + i) * R + r0 + x] = tile[x][i];
}

__global__ void transpose_ff(const float* __restrict__ in, float* __restrict__ out, int N) {
    __shared__ float tile[32][33];
    int r0 = blockIdx.x * 32, c0 = blockIdx.y * 32;
    int x = threadIdx.x, y = threadIdx.y;
    for (int i = y; i < 32; i += 8)
        tile[i][x] = in[(size_t)(r0 + i) * N + c0 + x];
    __syncthreads();
    for (int i = y; i < 32; i += 8)
        out[(size_t)(c0 + i) * N + r0 + x] = tile[x][i];
}

__global__ void ln_rope_kernel(const float* __restrict__ kvr,
                               __half* __restrict__ hkv, __half* __restrict__ hrot,
                               const float* __restrict__ w, const float* __restrict__ b) {
    __shared__ __align__(16) float row[4096];
    __shared__ float red[256];
    int rix = blockIdx.x;
    int l = rix & (Lseq - 1);
    size_t base = (size_t)rix * 4096;
    int tid = threadIdx.x;
    float s = 0.f;
    for (int i = tid; i < 4096; i += 256) { float v = kvr[base + i]; row[i] = v; s += v; }
    red[tid] = s; __syncthreads();
    for (int off = 128; off > 0; off >>= 1) {
        if (tid < off) red[tid] += red[tid + off];
        __syncthreads();
    }
    float mean = red[0] * (1.f / 4096.f);
    __syncthreads();
    float vs = 0.f;
    for (int i = tid; i < 4096; i += 256) { float d = row[i] - mean; vs += d * d; }
    red[tid] = vs; __syncthreads();
    for (int off = 128; off > 0; off >>= 1) {
        if (tid < off) red[tid] += red[tid + off];
        __syncthreads();
    }
    float inv = rsqrtf(red[0] * (1.f / 4096.f) + 1e-6f);
    __syncthreads();

    int tt = l >> 10;
    int rem = l & 1023;
    float hh = (float)(rem >> 5);
    float ww = (float)(rem & 31);
    float pos = (float)tt * (10.0f / 3.0f);
    float lo = floorf(pos); if (lo > 23.f) lo = 23.f;
    float hi = ceilf(pos);  if (hi > 23.f) hi = 23.f;
    float wgt = pos - lo;
    float pt = lo * (1.f - wgt) + hi * wgt;

    for (int i = tid; i < 2048; i += 256) {
        int j = 2 * i;
        float x1 = (row[j] - mean) * inv * w[j] + b[j];
        float x2 = (row[j + 1] - mean) * inv * w[j + 1] + b[j + 1];
        float theta;
        if (j < 1024) {
            int k = j & 511;
            theta = pt * powf(10000.f, -(float)(2 * k) / 1024.f);
        } else if (j < 2560) {
            int k = (j - 1024) % 768;
            theta = hh * powf(10000.f, -(float)(2 * k) / 1536.f);
        } else {
            int k = (j - 2560) % 768;
            theta = ww * powf(10000.f, -(float)(2 * k) / 1536.f);
        }
        float cc = cosf(theta), ss = sinf(theta);
        *(__half2*)&hkv[base + j]  = __floats2half2_rn(x1, x2);
        *(__half2*)&hrot[base + j] = __floats2half2_rn(x1 * cc - x2 * ss,
                                                       x1 * ss + x2 * cc);
    }
}

__global__ void ln_kernel(const float* __restrict__ in, float* __restrict__ out,
                          const float* __restrict__ w, const float* __restrict__ b) {
    __shared__ __align__(16) float row[4096];
    __shared__ float red[256];
    size_t base = (size_t)blockIdx.x * 4096;
    int tid = threadIdx.x;
    float s = 0.f;
    for (int i = tid; i < 4096; i += 256) { float v = in[base + i]; row[i] = v; s += v; }
    red[tid] = s; __syncthreads();
    for (int off = 128; off > 0; off >>= 1) {
        if (tid < off) red[tid] += red[tid + off];
        __syncthreads();
    }
    float mean = red[0] * (1.f / 4096.f);
    __syncthreads();
    float vs = 0.f;
    for (int i = tid; i < 4096; i += 256) { float d = row[i] - mean; vs += d * d; }
    red[tid] = vs; __syncthreads();
    for (int off = 128; off > 0; off >>= 1) {
        if (tid < off) red[tid] += red[tid + off];
        __syncthreads();
    }
    float inv = rsqrtf(red[0] * (1.f / 4096.f) + 1e-6f);
    for (int i = tid; i < 4096; i += 256)
        out[base + i] = (row[i] - mean) * inv * w[i] + b[i];
}

__global__ void softmax_h(const float* __restrict__ s, __half* __restrict__ o) {
    __shared__ __align__(16) float rowc[Lseq];
    __shared__ float red[256];
    const float* p = s + (size_t)blockIdx.x * Lseq;
    __half* q = o + (size_t)blockIdx.x * Lseq;
    int tid = threadIdx.x;
    float mx = -1e30f;
    for (int i = tid; i < Lseq; i += 256) { float v = p[i]; rowc[i] = v; mx = fmaxf(mx, v); }
    red[tid] = mx; __syncthreads();
    for (int off = 128; off > 0; off >>= 1) {
        if (tid < off) red[tid] = fmaxf(red[tid], red[tid + off]);
        __syncthreads();
    }
    mx = red[0];
    __syncthreads();
    float sum = 0.f;
    for (int i = tid; i < Lseq; i += 256) {
        float e = expf(rowc[i] - mx);
        rowc[i] = e;
        sum += e;
    }
    red[tid] = sum; __syncthreads();
    for (int off = 128; off > 0; off >>= 1) {
        if (tid < off) red[tid] += red[tid + off];
        __syncthreads();
    }
    float inv = 1.f / red[0];
    __syncthreads();
    for (int i = tid; i < Lseq; i += 256) q[i] = (__half)(rowc[i] * inv);
}

__global__ void bias_combine(const float* __restrict__ Wout, const float* __restrict__ bv,
                             const float* __restrict__ bout, float* __restrict__ bc) {
    __shared__ float red[128];
    int f = blockIdx.x;
    int tid = threadIdx.x;
    float s = 0.f;
    for (int e = tid; e < EDIM; e += 128) s += Wout[(size_t)f * EDIM + e] * bv[e];
    red[tid] = s; __syncthreads();
    for (int off = 64; off > 0; off >>= 1) {
        if (tid < off) red[tid] += red[tid + off];
        __syncthreads();
    }
    if (tid == 0) bc[f] = red[0] + bout[f];
}

// ---------------- launch ----------------
extern "C" void kernel_launch(void* const* d_in, const int* in_sizes, int n_in,
                              void* d_out, int out_size) {
    const float* cube      = (const float*)d_in[0];
    const float* query     = (const float*)d_in[1];
    const float* kv_proj_w = (const float*)d_in[2];
    const float* ln_q_w    = (const float*)d_in[3];
    const float* ln_q_b    = (const float*)d_in[4];
    const float* ln_kv_w   = (const float*)d_in[5];
    const float* ln_kv_b   = (const float*)d_in[6];
    const float* ln_post_w = (const float*)d_in[7];
    const float* ln_post_b = (const float*)d_in[8];
    const float* in_proj_w = (const float*)d_in[9];
    const float* in_proj_b = (const float*)d_in[10];
    const float* out_proj_w= (const float*)d_in[11];
    const float* out_proj_b= (const float*)d_in[12];
    const float* proj      = (const float*)d_in[13];
    float* out = (float*)d_out;

    float *kvraw, *scores, *qn, *qp, *qk, *U, *ctx, *out1, *ln2, *WkT, *projT, *bc;
    __half *hcube, *hw, *hkv, *hrot, *hkvT, *hattn, *hqk;
    cudaGetSymbolAddress((void**)&kvraw, g_kvraw);
    cudaGetSymbolAddress((void**)&hcube, g_hcube);
    cudaGetSymbolAddress((void**)&hw,    g_hw);
    cudaGetSymbolAddress((void**)&hkv,   g_hkv);
    cudaGetSymbolAddress((void**)&hrot,  g_hrot);
    cudaGetSymbolAddress((void**)&hkvT,  g_hkvT);
    cudaGetSymbolAddress((void**)&scores,g_scores);
    cudaGetSymbolAddress((void**)&hattn, g_hattn);
    cudaGetSymbolAddress((void**)&qn,    g_qn);
    cudaGetSymbolAddress((void**)&qp,    g_qp);
    cudaGetSymbolAddress((void**)&qk,    g_qk);
    cudaGetSymbolAddress((void**)&hqk,   g_hqk);
    cudaGetSymbolAddress((void**)&U,     g_U);
    cudaGetSymbolAddress((void**)&ctx,   g_ctx);
    cudaGetSymbolAddress((void**)&out1,  g_out1);
    cudaGetSymbolAddress((void**)&ln2,   g_ln2);
    cudaGetSymbolAddress((void**)&WkT,   g_WkT);
    cudaGetSymbolAddress((void**)&projT, g_projT);
    cudaGetSymbolAddress((void**)&bc,    g_bc);

    cudaFuncSetAttribute(gemm_h, cudaFuncAttributeMaxDynamicSharedMemorySize, GSMB);

    const size_t EE = (size_t)EDIM * EDIM;
    const float isq = 0.08838834764831845f;

    // conversions / prep
    cvt_h<<<(NROWS * VD / 4 + 255) / 256, 256>>>(cube, hcube, NROWS * VD / 4);
    cvt_h<<<(EDIM * VD / 4 + 255) / 256, 256>>>(kv_proj_w, hw, EDIM * VD / 4);
    transpose_ff<<<dim3(EDIM / 32, EDIM / 32), dim3(32, 8)>>>(in_proj_w + EE, WkT, EDIM);
    transpose_ff<<<dim3(EDIM / 32, EDIM / 32), dim3(32, 8)>>>(proj, projT, EDIM);
    bias_combine<<<EDIM, 128>>>(out_proj_w, in_proj_b + 2 * EDIM, out_proj_b, bc);

    // 1) kvraw = cube @ kv_proj_w^T (fp16 MMA, fp32 out)
    gemm_h<<<dim3(EDIM / 256, NROWS / 128, 1), 256, GSMB>>>(
        hcube, VD, 0, hw, VD, 0, kvraw, EDIM, 0, VD, 1.f);
    // 2) LN + RoPE -> hkv, hrot
    ln_rope_kernel<<<NROWS, 256>>>(kvraw, hkv, hrot, ln_kv_w, ln_kv_b);
    // 3) hkvT
    transpose_hh<<<dim3(Lseq / 32, EDIM / 32, Bb), dim3(32, 8)>>>(
        hkv, hkvT, Lseq, EDIM, (size_t)Lseq * EDIM, (size_t)EDIM * Lseq);

    // 4) q path (fp32)
    ln_kernel<<<NQ, 256>>>(query, qn, ln_q_w, ln_q_b);
    init_rows<<<dim3(EDIM / 256, NQ), 256>>>(qp, in_proj_b, EDIM);
    sg_lin<<<dim3(EDIM / 64, 1, 8), 256>>>(qn, EDIM, in_proj_w, EDIM, qp, EDIM, 512);
    // 5) qk (fp32 per head) -> fp16
    init_rows<<<dim3(EDIM / 256, 2048), 256>>>(qk, nullptr, EDIM);
    sg_qk<<<dim3(EDIM / 64, 1, NH), 256>>>(qp, WkT, qk);
    cvt_h<<<(2048 * EDIM / 4 + 255) / 256, 256>>>(qk, hqk, 2048 * EDIM / 4);

    // 6) scores = hqk @ hrot_b^T * isq
    gemm_h<<<dim3(Lseq / 256, 2048 / 128, Bb), 256, GSMB>>>(
        hqk, EDIM, 0, hrot, EDIM, (size_t)Lseq * EDIM,
        scores, Lseq, (size_t)2048 * Lseq, EDIM, isq);
    // 7) softmax -> fp16
    softmax_h<<<Bb * 2048, 256>>>(scores, hattn);
    // 8) U = attn @ kvT^T (fp32 out)
    gemm_h<<<dim3(EDIM / 256, 2048 / 128, Bb), 256, GSMB>>>(
        hattn, Lseq, (size_t)2048 * Lseq, hkvT, Lseq, (size_t)EDIM * Lseq,
        U, EDIM, (size_t)2048 * EDIM, Lseq, 1.f);

    // 9) ctx = U @ Wv_h^T (fp32)
    init_rows<<<dim3(EDIM / 256, 128), 256>>>(ctx, nullptr, EDIM);
    sg_vproj<<<dim3(2, 1, Bb * NH * 4), 256>>>(U, in_proj_w + 2 * EE, ctx);
    // 10) out1 = ctx @ Wout^T + bc
    init_rows<<<dim3(EDIM / 256, 128), 256>>>(out1, bc, EDIM);
    sg_lin<<<dim3(EDIM / 64, 2, 8), 256>>>(ctx, EDIM, out_proj_w, EDIM, out1, EDIM, 512);
    // 11) post-LN
    ln_kernel<<<128, 256>>>(out1, ln2, ln_post_w, ln_post_b);
    // 12) out = ln2 @ projT^T
    init_rows<<<dim3(EDIM / 256, 128), 256>>>(out, nullptr, EDIM);
    sg_lin<<<dim3(EDIM / 64, 2, 8), 256>>>(ln2, EDIM, projT, EDIM, out, EDIM, 512);
}

// round 14
// speedup vs baseline: 1.5321x; 1.5321x over previous
#include <cuda_runtime.h>
#include <cuda_fp16.h>
#include <math.h>
#include <stdint.h>

#define EDIM 4096
#define NH   32
#define HD   128
#define Lseq 8192
#define Bb   2
#define VD   1536
#define NQ   64
#define NROWS (Bb*Lseq)

// ---------------- scratch ----------------
__device__ float  g_kvraw[NROWS * EDIM];
__device__ __half g_hcube[NROWS * VD];
__device__ __half g_hw[EDIM * VD];
__device__ __half g_hkv[NROWS * EDIM];
__device__ __half g_hrot[NROWS * EDIM];
__device__ __half g_hkvT[(size_t)Bb * EDIM * Lseq];
__device__ float  g_scores[(size_t)Bb * 2048 * Lseq];
__device__ __half g_hattn[(size_t)Bb * 2048 * Lseq];
__device__ float  g_qn[NQ * EDIM];
__device__ float  g_qp[NQ * EDIM];
__device__ float  g_qk[2048 * EDIM];
__device__ __half g_hqk[2048 * EDIM];
__device__ float  g_U[(size_t)Bb * 2048 * EDIM];
__device__ float  g_ctx[128 * EDIM];
__device__ float  g_out1[128 * EDIM];
__device__ float  g_ln2[128 * EDIM];
__device__ float  g_WkT[(size_t)EDIM * EDIM];
__device__ float  g_projT[(size_t)EDIM * EDIM];
__device__ float  g_bc[EDIM];
// rope tables: [0,4096) t-part (8x512), [4096,28672) h-part (32x768), [28672,53248) w-part
#define TAB_N 53248
__device__ float  g_tabc[TAB_N];
__device__ float  g_tabs[TAB_N];

// ---------------- asm helpers ----------------
__device__ __forceinline__ void mma_f16(float c[4], uint32_t a0, uint32_t a1,
                                        uint32_t a2, uint32_t a3,
                                        uint32_t b0, uint32_t b1) {
    asm("mma.sync.aligned.m16n8k16.row.col.f32.f16.f16.f32 "
        "{%0,%1,%2,%3}, {%4,%5,%6,%7}, {%8,%9}, {%0,%1,%2,%3};"
        : "+f"(c[0]), "+f"(c[1]), "+f"(c[2]), "+f"(c[3])
        : "r"(a0), "r"(a1), "r"(a2), "r"(a3), "r"(b0), "r"(b1));
}
__device__ __forceinline__ void ldsm4(uint32_t& r0, uint32_t& r1, uint32_t& r2,
                                      uint32_t& r3, uint32_t a) {
    asm volatile("ldmatrix.sync.aligned.m8n8.x4.shared.b16 {%0,%1,%2,%3}, [%4];"
                 : "=r"(r0), "=r"(r1), "=r"(r2), "=r"(r3) : "r"(a));
}
__device__ __forceinline__ void cp16(uint32_t s, const void* g) {
    asm volatile("cp.async.cg.shared.global [%0], [%1], 16;" :: "r"(s), "l"(g));
}
#define CP_COMMIT() asm volatile("cp.async.commit_group;")
#define CP_WAIT0()  asm volatile("cp.async.wait_group 0;" ::: "memory")

// ---------------- fp16 TN GEMM (R7-proven): C(fp32) = alpha*(A . B^T) ----------------
// Block 128x256, 8 warps 64x64. M%128==0, N%256==0, K%32==0. 2-stage cp.async + ldmatrix.
#define GSMB 61440
__global__ __launch_bounds__(256, 1)
void gemm_h(const __half* __restrict__ A, int lda, size_t sAz,
            const __half* __restrict__ B, int ldb, size_t sBz,
            float* __restrict__ C, int ldc, size_t sCz,
            int K, float alpha) {
    extern __shared__ __align__(16) uint32_t sm[];
    uint32_t smB = (uint32_t)__cvta_generic_to_shared(sm);
    int t = threadIdx.x, lane = t & 31, wid = t >> 5;
    A += (size_t)blockIdx.z * sAz;
    B += (size_t)blockIdx.z * sBz;
    C += (size_t)blockIdx.z * sCz;
    int m0 = blockIdx.y * 128, n0 = blockIdx.x * 256;
    int wm = (wid & 1) * 64, wn = (wid >> 1) * 64;
    int lr = lane >> 2, lc = lane & 3;

    int ar = t >> 1, ac = (t & 1) * 2;
    const __half* gA = A + (size_t)(m0 + ar) * lda + ac * 8;
    const __half* gB = B + (size_t)(n0 + t) * ldb;
    uint32_t sAaddr = smB + ar * 80 + ac * 16;
    uint32_t sBaddr = smB + 20480 + t * 80;

    uint32_t aBase = smB + (wm + (lane & 15)) * 80 + ((lane >> 4) & 1) * 16;
    uint32_t bBase = smB + 20480 +
                     (wn + (lane & 7) + ((lane >> 4) & 1) * 8) * 80 +
                     ((lane >> 3) & 1) * 16;

    float acc[4][8][4];
#pragma unroll
    for (int i = 0; i < 4; i++)
#pragma unroll
        for (int j = 0; j < 8; j++)
#pragma unroll
            for (int v = 0; v < 4; v++) acc[i][j][v] = 0.f;

    // prologue: stage 0
    cp16(sAaddr, gA); cp16(sAaddr + 16, gA + 8);
#pragma unroll
    for (int c = 0; c < 4; c++) cp16(sBaddr + c * 16, gB + c * 8);
    CP_COMMIT(); CP_WAIT0(); __syncthreads();

    int st = 0;
    for (int k0 = 0; k0 < K; k0 += 32) {
        bool more = (k0 + 32) < K;
        if (more) {
            int ns = st ^ 1;
            uint32_t d = sAaddr + ns * 10240;
            cp16(d, gA + k0 + 32); cp16(d + 16, gA + k0 + 40);
            uint32_t e = sBaddr + ns * 20480;
#pragma unroll
            for (int c = 0; c < 4; c++) cp16(e + c * 16, gB + k0 + 32 + c * 8);
            CP_COMMIT();
        }
        uint32_t sa = aBase + st * 10240;
        uint32_t sb = bBase + st * 20480;
#pragma unroll
        for (int kk = 0; kk < 2; kk++) {
            uint32_t af[4][4], bf[8][2];
#pragma unroll
            for (int i = 0; i < 4; i++)
                ldsm4(af[i][0], af[i][1], af[i][2], af[i][3],
                      sa + i * 1280 + kk * 32);
#pragma unroll
            for (int jp = 0; jp < 4; jp++)
                ldsm4(bf[2 * jp][0], bf[2 * jp][1], bf[2 * jp + 1][0],
                      bf[2 * jp + 1][1], sb + jp * 1280 + kk * 32);
#pragma unroll
            for (int i = 0; i < 4; i++)
#pragma unroll
                for (int j = 0; j < 8; j++)
                    mma_f16(acc[i][j], af[i][0], af[i][1], af[i][2], af[i][3],
                            bf[j][0], bf[j][1]);
        }
        if (more) { CP_WAIT0(); __syncthreads(); st ^= 1; }
    }

#pragma unroll
    for (int i = 0; i < 4; i++) {
        int row = m0 + wm + i * 16 + lr;
#pragma unroll
        for (int j = 0; j < 8; j++) {
            int col = n0 + wn + j * 8 + lc * 2;
            *(float2*)&C[(size_t)row * ldc + col] =
                make_float2(acc[i][j][0] * alpha, acc[i][j][1] * alpha);
            *(float2*)&C[(size_t)(row + 8) * ldc + col] =
                make_float2(acc[i][j][2] * alpha, acc[i][j][3] * alpha);
        }
    }
}

// ---------------- fp32 split-K GEMM (small), atomic accumulate ----------------
__device__ __forceinline__
void sg_body(const float* __restrict__ A, int lda,
             const float* __restrict__ B, int ldb,
             float* __restrict__ C, int ldc, int n0, int Ks) {
    __shared__ float As[8][64], Bs[8][64];
    int t = threadIdx.x;
    int row = t & 63, kc = t >> 6;
    int ty = t >> 4, tx = t & 15;
    float acc[4][4];
#pragma unroll
    for (int i = 0; i < 4; i++)
#pragma unroll
        for (int j = 0; j < 4; j++) acc[i][j] = 0.f;
    for (int k0 = 0; k0 < Ks; k0 += 8) {
        float2 a = *(const float2*)&A[(size_t)row * lda + k0 + kc * 2];
        float2 b = *(const float2*)&B[(size_t)(n0 + row) * ldb + k0 + kc * 2];
        As[kc * 2][row] = a.x; As[kc * 2 + 1][row] = a.y;
        Bs[kc * 2][row] = b.x; Bs[kc * 2 + 1][row] = b.y;
        __syncthreads();
#pragma unroll
        for (int k = 0; k < 8; k++) {
            float av[4] = {As[k][ty * 4], As[k][ty * 4 + 1],
                           As[k][ty * 4 + 2], As[k][ty * 4 + 3]};
            float bv[4] = {Bs[k][tx * 4], Bs[k][tx * 4 + 1],
                           Bs[k][tx * 4 + 2], Bs[k][tx * 4 + 3]};
#pragma unroll
            for (int i = 0; i < 4; i++)
#pragma unroll
                for (int j = 0; j < 4; j++)
                    acc[i][j] = fmaf(av[i], bv[j], acc[i][j]);
        }
        __syncthreads();
    }
#pragma unroll
    for (int i = 0; i < 4; i++)
#pragma unroll
        for (int j = 0; j < 4; j++)
            atomicAdd(&C[(size_t)(ty * 4 + i) * ldc + n0 + tx * 4 + j], acc[i][j]);
}

__global__ __launch_bounds__(256)
void sg_lin(const float* A, int lda, const float* B, int ldb,
            float* C, int ldc, int Ks) {
    sg_body(A + (size_t)blockIdx.y * 64 * lda + (size_t)blockIdx.z * Ks, lda,
            B + (size_t)blockIdx.z * Ks, ldb,
            C + (size_t)blockIdx.y * 64 * ldc, ldc, blockIdx.x * 64, Ks);
}
__global__ __launch_bounds__(256)
void sg_qk(const float* qp, const float* WkT, float* qk) {
    int h = blockIdx.z;
    sg_body(qp + h * 128, EDIM, WkT + h * 128, EDIM,
            qk + (size_t)h * 64 * EDIM, EDIM, blockIdx.x * 64, 128);
}
__global__ __launch_bounds__(256)
void sg_vproj(const float* U, const float* Wv, float* ctx) {
    int z = blockIdx.z;
    int bh = z >> 2, s = z & 3;
    int b = bh >> 5, h = bh & 31;
    sg_body(U + (size_t)bh * 64 * EDIM + s * 1024, EDIM,
            Wv + (size_t)h * 128 * EDIM + s * 1024, EDIM,
            ctx + (size_t)b * 64 * EDIM + h * 128, EDIM, blockIdx.x * 64, 1024);
}

__global__ void init_rows(float* C, const float* bias, int ld) {
    int f = blockIdx.x * 256 + threadIdx.x;
    C[(size_t)blockIdx.y * ld + f] = bias ? bias[f] : 0.f;
}

// ---------------- rope table build (one-time; exact same math as before) ----------------
__global__ void build_rope_tab(float* __restrict__ tc, float* __restrict__ ts) {
    int idx = blockIdx.x * 256 + threadIdx.x;
    if (idx >= TAB_N) return;
    float theta;
    if (idx < 4096) {
        int t = idx >> 9, i = idx & 511;
        float pos = (float)t * (10.0f / 3.0f);
        float lo = floorf(pos); if (lo > 23.f) lo = 23.f;
        float hi = ceilf(pos);  if (hi > 23.f) hi = 23.f;
        float wgt = pos - lo;
        float pt = lo * (1.f - wgt) + hi * wgt;
        int j = 2 * i;
        int k = j & 511;
        theta = pt * powf(10000.f, -(float)(2 * k) / 1024.f);
    } else if (idx < 28672) {
        int r = idx - 4096;
        int hh = r / 768, ii = r % 768;        // ii = i-512, i in [512,1280)
        int j = 2 * (ii + 512);
        int k = (j - 1024) % 768;
        theta = (float)hh * powf(10000.f, -(float)(2 * k) / 1536.f);
    } else {
        int r = idx - 28672;
        int ww = r / 768, ii = r % 768;        // ii = i-1280
        int j = 2 * (ii + 1280);
        int k = (j - 2560) % 768;
        theta = (float)ww * powf(10000.f, -(float)(2 * k) / 1536.f);
    }
    tc[idx] = cosf(theta);
    ts[idx] = sinf(theta);
}

// ---------------- elementwise / misc ----------------
__global__ void cvt_h(const float* __restrict__ in, __half* __restrict__ out, int n4) {
    int i = blockIdx.x * blockDim.x + threadIdx.x;
    if (i < n4) {
        float4 v = ((const float4*)in)[i];
        ((__half2*)out)[i * 2]     = __floats2half2_rn(v.x, v.y);
        ((__half2*)out)[i * 2 + 1] = __floats2half2_rn(v.z, v.w);
    }
}

__global__ void transpose_hh(const __half* __restrict__ in, __half* __restrict__ out,
                             int R, int Cc, size_t sIn, size_t sOut) {
    __shared__ __half tile[32][33];
    in += (size_t)blockIdx.z * sIn;
    out += (size_t)blockIdx.z * sOut;
    int r0 = blockIdx.x * 32, c0 = blockIdx.y * 32;
    int x = threadIdx.x, y = threadIdx.y;
    for (int i = y; i < 32; i += 8)
        tile[i][x] = in[(size_t)(r0 + i) * Cc + c0 + x];
    __syncthreads();
    for (int i = y; i < 32; i += 8)
        out[(size_t)(c0 + i) * R + r0 + x] = tile[x][i];
}

__global__ void transpose_ff(const float* __restrict__ in, float* __restrict__ out, int N) {
    __shared__ float tile[32][33];
    int r0 = blockIdx.x * 32, c0 = blockIdx.y * 32;
    int x = threadIdx.x, y = threadIdx.y;
    for (int i = y; i < 32; i += 8)
        tile[i][x] = in[(size_t)(r0 + i) * N + c0 + x];
    __syncthreads();
    for (int i = y; i < 32; i += 8)
        out[(size_t)(c0 + i) * N + r0 + x] = tile[x][i];
}

__global__ void ln_rope_kernel(const float* __restrict__ kvr,
                               __half* __restrict__ hkv, __half* __restrict__ hrot,
                               const float* __restrict__ w, const float* __restrict__ b,
                               const float* __restrict__ tc, const float* __restrict__ ts) {
    __shared__ __align__(16) float row[4096];
    __shared__ float red[256];
    int rix = blockIdx.x;
    int l = rix & (Lseq - 1);
    size_t base = (size_t)rix * 4096;
    int tid = threadIdx.x;
    float s = 0.f;
    for (int i = tid; i < 4096; i += 256) { float v = kvr[base + i]; row[i] = v; s += v; }
    red[tid] = s; __syncthreads();
    for (int off = 128; off > 0; off >>= 1) {
        if (tid < off) red[tid] += red[tid + off];
        __syncthreads();
    }
    float mean = red[0] * (1.f / 4096.f);
    __syncthreads();
    float vs = 0.f;
    for (int i = tid; i < 4096; i += 256) { float d = row[i] - mean; vs += d * d; }
    red[tid] = vs; __syncthreads();
    for (int off = 128; off > 0; off >>= 1) {
        if (tid < off) red[tid] += red[tid + off];
        __syncthreads();
    }
    float inv = rsqrtf(red[0] * (1.f / 4096.f) + 1e-6f);
    __syncthreads();

    int tt = l >> 10;
    int rem = l & 1023;
    int hh = rem >> 5;
    int ww = rem & 31;
    int baseT = tt * 512;
    int baseH = 4096 + hh * 768 - 512;     // index with +i
    int baseW = 28672 + ww * 768 - 1280;

    for (int i = tid; i < 2048; i += 256) {
        int j = 2 * i;
        float x1 = (row[j] - mean) * inv * w[j] + b[j];
        float x2 = (row[j + 1] - mean) * inv * w[j + 1] + b[j + 1];
        int o = (i < 512) ? (baseT + i) : (i < 1280) ? (baseH + i) : (baseW + i);
        float cc = tc[o], ss = ts[o];
        *(__half2*)&hkv[base + j]  = __floats2half2_rn(x1, x2);
        *(__half2*)&hrot[base + j] = __floats2half2_rn(x1 * cc - x2 * ss,
                                                       x1 * ss + x2 * cc);
    }
}

__global__ void ln_kernel(const float* __restrict__ in, float* __restrict__ out,
                          const float* __restrict__ w, const float* __restrict__ b) {
    __shared__ __align__(16) float row[4096];
    __shared__ float red[256];
    size_t base = (size_t)blockIdx.x * 4096;
    int tid = threadIdx.x;
    float s = 0.f;
    for (int i = tid; i < 4096; i += 256) { float v = in[base + i]; row[i] = v; s += v; }
    red[tid] = s; __syncthreads();
    for (int off = 128; off > 0; off >>= 1) {
        if (tid < off) red[tid] += red[tid + off];
        __syncthreads();
    }
    float mean = red[0] * (1.f / 4096.f);
    __syncthreads();
    float vs = 0.f;
    for (int i = tid; i < 4096; i += 256) { float d = row[i] - mean; vs += d * d; }
    red[tid] = vs; __syncthreads();
    for (int off = 128; off > 0; off >>= 1) {
        if (tid < off) red[tid] += red[tid + off];
        __syncthreads();
    }
    float inv = rsqrtf(red[0] * (1.f / 4096.f) + 1e-6f);
    for (int i = tid; i < 4096; i += 256)
        out[base + i] = (row[i] - mean) * inv * w[i] + b[i];
}

__global__ void softmax_h(const float* __restrict__ s, __half* __restrict__ o) {
    __shared__ __align__(16) float rowc[Lseq];
    __shared__ float red[256];
    const float* p = s + (size_t)blockIdx.x * Lseq;
    __half* q = o + (size_t)blockIdx.x * Lseq;
    int tid = threadIdx.x;
    float mx = -1e30f;
    for (int i = tid; i < Lseq; i += 256) { float v = p[i]; rowc[i] = v; mx = fmaxf(mx, v); }
    red[tid] = mx; __syncthreads();
    for (int off = 128; off > 0; off >>= 1) {
        if (tid < off) red[tid] = fmaxf(red[tid], red[tid + off]);
        __syncthreads();
    }
    mx = red[0];
    __syncthreads();
    float sum = 0.f;
    for (int i = tid; i < Lseq; i += 256) {
        float e = expf(rowc[i] - mx);
        rowc[i] = e;
        sum += e;
    }
    red[tid] = sum; __syncthreads();
    for (int off = 128; off > 0; off >>= 1) {
        if (tid < off) red[tid] += red[tid + off];
        __syncthreads();
    }
    float inv = 1.f / red[0];
    __syncthreads();
    for (int i = tid; i < Lseq; i += 256) q[i] = (__half)(rowc[i] * inv);
}

__global__ void bias_combine(const float* __restrict__ Wout, const float* __restrict__ bv,
                             const float* __restrict__ bout, float* __restrict__ bc) {
    __shared__ float red[128];
    int f = blockIdx.x;
    int tid = threadIdx.x;
    float s = 0.f;
    for (int e = tid; e < EDIM; e += 128) s += Wout[(size_t)f * EDIM + e] * bv[e];
    red[tid] = s; __syncthreads();
    for (int off = 64; off > 0; off >>= 1) {
        if (tid < off) red[tid] += red[tid + off];
        __syncthreads();
    }
    if (tid == 0) bc[f] = red[0] + bout[f];
}

// ---------------- launch ----------------
extern "C" void kernel_launch(void* const* d_in, const int* in_sizes, int n_in,
                              void* d_out, int out_size) {
    const float* cube      = (const float*)d_in[0];
    const float* query     = (const float*)d_in[1];
    const float* kv_proj_w = (const float*)d_in[2];
    const float* ln_q_w    = (const float*)d_in[3];
    const float* ln_q_b    = (const float*)d_in[4];
    const float* ln_kv_w   = (const float*)d_in[5];
    const float* ln_kv_b   = (const float*)d_in[6];
    const float* ln_post_w = (const float*)d_in[7];
    const float* ln_post_b = (const float*)d_in[8];
    const float* in_proj_w = (const float*)d_in[9];
    const float* in_proj_b = (const float*)d_in[10];
    const float* out_proj_w= (const float*)d_in[11];
    const float* out_proj_b= (const float*)d_in[12];
    const float* proj      = (const float*)d_in[13];
    float* out = (float*)d_out;

    float *kvraw, *scores, *qn, *qp, *qk, *U, *ctx, *out1, *ln2, *WkT, *projT, *bc;
    float *tabc, *tabs;
    __half *hcube, *hw, *hkv, *hrot, *hkvT, *hattn, *hqk;
    cudaGetSymbolAddress((void**)&kvraw, g_kvraw);
    cudaGetSymbolAddress((void**)&hcube, g_hcube);
    cudaGetSymbolAddress((void**)&hw,    g_hw);
    cudaGetSymbolAddress((void**)&hkv,   g_hkv);
    cudaGetSymbolAddress((void**)&hrot,  g_hrot);
    cudaGetSymbolAddress((void**)&hkvT,  g_hkvT);
    cudaGetSymbolAddress((void**)&scores,g_scores);
    cudaGetSymbolAddress((void**)&hattn, g_hattn);
    cudaGetSymbolAddress((void**)&qn,    g_qn);
    cudaGetSymbolAddress((void**)&qp,    g_qp);
    cudaGetSymbolAddress((void**)&qk,    g_qk);
    cudaGetSymbolAddress((void**)&hqk,   g_hqk);
    cudaGetSymbolAddress((void**)&U,     g_U);
    cudaGetSymbolAddress((void**)&ctx,   g_ctx);
    cudaGetSymbolAddress((void**)&out1,  g_out1);
    cudaGetSymbolAddress((void**)&ln2,   g_ln2);
    cudaGetSymbolAddress((void**)&WkT,   g_WkT);
    cudaGetSymbolAddress((void**)&projT, g_projT);
    cudaGetSymbolAddress((void**)&bc,    g_bc);
    cudaGetSymbolAddress((void**)&tabc,  g_tabc);
    cudaGetSymbolAddress((void**)&tabs,  g_tabs);

    cudaFuncSetAttribute(gemm_h, cudaFuncAttributeMaxDynamicSharedMemorySize, GSMB);

    const size_t EE = (size_t)EDIM * EDIM;
    const float isq = 0.08838834764831845f;

    // conversions / prep
    build_rope_tab<<<(TAB_N + 255) / 256, 256>>>(tabc, tabs);
    cvt_h<<<(NROWS * VD / 4 + 255) / 256, 256>>>(cube, hcube, NROWS * VD / 4);
    cvt_h<<<(EDIM * VD / 4 + 255) / 256, 256>>>(kv_proj_w, hw, EDIM * VD / 4);
    transpose_ff<<<dim3(EDIM / 32, EDIM / 32), dim3(32, 8)>>>(in_proj_w + EE, WkT, EDIM);
    transpose_ff<<<dim3(EDIM / 32, EDIM / 32), dim3(32, 8)>>>(proj, projT, EDIM);
    bias_combine<<<EDIM, 128>>>(out_proj_w, in_proj_b + 2 * EDIM, out_proj_b, bc);

    // 1) kvraw = cube @ kv_proj_w^T (fp16 MMA, fp32 out)
    gemm_h<<<dim3(EDIM / 256, NROWS / 128, 1), 256, GSMB>>>(
        hcube, VD, 0, hw, VD, 0, kvraw, EDIM, 0, VD, 1.f);
    // 2) LN + RoPE -> hkv, hrot (table-driven)
    ln_rope_kernel<<<NROWS, 256>>>(kvraw, hkv, hrot, ln_kv_w, ln_kv_b, tabc, tabs);
    // 3) hkvT
    transpose_hh<<<dim3(Lseq / 32, EDIM / 32, Bb), dim3(32, 8)>>>(
        hkv, hkvT, Lseq, EDIM, (size_t)Lseq * EDIM, (size_t)EDIM * Lseq);

    // 4) q path (fp32)
    ln_kernel<<<NQ, 256>>>(query, qn, ln_q_w, ln_q_b);
    init_rows<<<dim3(EDIM / 256, NQ), 256>>>(qp, in_proj_b, EDIM);
    sg_lin<<<dim3(EDIM / 64, 1, 8), 256>>>(qn, EDIM, in_proj_w, EDIM, qp, EDIM, 512);
    // 5) qk (fp32 per head) -> fp16
    init_rows<<<dim3(EDIM / 256, 2048), 256>>>(qk, nullptr, EDIM);
    sg_qk<<<dim3(EDIM / 64, 1, NH), 256>>>(qp, WkT, qk);
    cvt_h<<<(2048 * EDIM / 4 + 255) / 256, 256>>>(qk, hqk, 2048 * EDIM / 4);

    // 6) scores = hqk @ hrot_b^T * isq
    gemm_h<<<dim3(Lseq / 256, 2048 / 128, Bb), 256, GSMB>>>(
        hqk, EDIM, 0, hrot, EDIM, (size_t)Lseq * EDIM,
        scores, Lseq, (size_t)2048 * Lseq, EDIM, isq);
    // 7) softmax -> fp16
    softmax_h<<<Bb * 2048, 256>>>(scores, hattn);
    // 8) U = attn @ kvT^T (fp32 out)
    gemm_h<<<dim3(EDIM / 256, 2048 / 128, Bb), 256, GSMB>>>(
        hattn, Lseq, (size_t)2048 * Lseq, hkvT, Lseq, (size_t)EDIM * Lseq,
        U, EDIM, (size_t)2048 * EDIM, Lseq, 1.f);

    // 9) ctx = U @ Wv_h^T (fp32)
    init_rows<<<dim3(EDIM / 256, 128), 256>>>(ctx, nullptr, EDIM);
    sg_vproj<<<dim3(2, 1, Bb * NH * 4), 256>>>(U, in_proj_w + 2 * EE, ctx);
    // 10) out1 = ctx @ Wout^T + bc
    init_rows<<<dim3(EDIM / 256, 128), 256>>>(out1, bc, EDIM);
    sg_lin<<<dim3(EDIM / 64, 2, 8), 256>>>(ctx, EDIM, out_proj_w, EDIM, out1, EDIM, 512);
    // 11) post-LN
    ln_kernel<<<128, 256>>>(out1, ln2, ln_post_w, ln_post_b);
    // 12) out = ln2 @ projT^T
    init_rows<<<dim3(EDIM / 256, 128), 256>>>(out, nullptr, EDIM);
    sg_lin<<<dim3(EDIM / 64, 2, 8), 256>>>(ln2, EDIM, projT, EDIM, out, EDIM, 512);
}

// round 15
// speedup vs baseline: 1.8091x; 1.1808x over previous
#include <cuda_runtime.h>
#include <cuda_fp16.h>
#include <math.h>
#include <stdint.h>

#define EDIM 4096
#define NH   32
#define HD   128
#define Lseq 8192
#define Bb   2
#define VD   1536
#define NQ   64
#define NROWS (Bb*Lseq)

// ---------------- scratch ----------------
__device__ float  g_kvraw[NROWS * EDIM];
__device__ __half g_hcube[NROWS * VD];
__device__ __half g_hw[EDIM * VD];
__device__ __half g_hkv[NROWS * EDIM];
__device__ __half g_hrot[NROWS * EDIM];
__device__ __half g_hkvT[(size_t)Bb * EDIM * Lseq];
__device__ float  g_scores[(size_t)Bb * 2048 * Lseq];
__device__ __half g_hattn[(size_t)Bb * 2048 * Lseq];
__device__ float  g_qn[NQ * EDIM];
__device__ float  g_qp[NQ * EDIM];
__device__ float  g_qk[2048 * EDIM];
__device__ __half g_hqk[2048 * EDIM];
__device__ float  g_U[(size_t)Bb * 2048 * EDIM];
__device__ float  g_ctx[128 * EDIM];
__device__ float  g_out1[128 * EDIM];
__device__ float  g_ln2[128 * EDIM];
__device__ float  g_WkT[(size_t)EDIM * EDIM];
__device__ float  g_projT[(size_t)EDIM * EDIM];
__device__ float  g_bc[EDIM];
#define TAB_N 53248
__device__ float  g_tabc[TAB_N];
__device__ float  g_tabs[TAB_N];

// ---------------- asm helpers ----------------
__device__ __forceinline__ void mma_f16(float c[4], uint32_t a0, uint32_t a1,
                                        uint32_t a2, uint32_t a3,
                                        uint32_t b0, uint32_t b1) {
    asm("mma.sync.aligned.m16n8k16.row.col.f32.f16.f16.f32 "
        "{%0,%1,%2,%3}, {%4,%5,%6,%7}, {%8,%9}, {%0,%1,%2,%3};"
        : "+f"(c[0]), "+f"(c[1]), "+f"(c[2]), "+f"(c[3])
        : "r"(a0), "r"(a1), "r"(a2), "r"(a3), "r"(b0), "r"(b1));
}
__device__ __forceinline__ void ldsm4(uint32_t& r0, uint32_t& r1, uint32_t& r2,
                                      uint32_t& r3, uint32_t a) {
    asm volatile("ldmatrix.sync.aligned.m8n8.x4.shared.b16 {%0,%1,%2,%3}, [%4];"
                 : "=r"(r0), "=r"(r1), "=r"(r2), "=r"(r3) : "r"(a));
}
__device__ __forceinline__ void cp16(uint32_t s, const void* g) {
    asm volatile("cp.async.cg.shared.global [%0], [%1], 16;" :: "r"(s), "l"(g));
}
#define CP_COMMIT() asm volatile("cp.async.commit_group;")
#define CP_WAIT0()  asm volatile("cp.async.wait_group 0;" ::: "memory")

// ---------------- fp16 TN GEMM v3: C(fp32) = alpha*(A . B^T) ----------------
// Block 128x128, 8 warps of 64x32. M%128==0, N%128==0, K%32==0.
// 2-stage cp.async + ldmatrix; 2 CTAs/SM (launch_bounds(256,2)).
#define GSMB 40960
__global__ __launch_bounds__(256, 2)
void gemm_h(const __half* __restrict__ A, int lda, size_t sAz,
            const __half* __restrict__ B, int ldb, size_t sBz,
            float* __restrict__ C, int ldc, size_t sCz,
            int K, float alpha) {
    extern __shared__ __align__(16) uint32_t sm[];
    uint32_t smB = (uint32_t)__cvta_generic_to_shared(sm);
    int t = threadIdx.x, lane = t & 31, wid = t >> 5;
    A += (size_t)blockIdx.z * sAz;
    B += (size_t)blockIdx.z * sBz;
    C += (size_t)blockIdx.z * sCz;
    int m0 = blockIdx.y * 128, n0 = blockIdx.x * 128;
    int wm = (wid & 1) * 64, wn = (wid >> 1) * 32;
    int lr = lane >> 2, lc = lane & 3;

    // staging: rows 64B each, 2 threads x 2 chunks of 16B per row; row stride 80 B
    int ar = t >> 1, ac = (t & 1) * 2;
    const __half* gA = A + (size_t)(m0 + ar) * lda + ac * 8;
    const __half* gB = B + (size_t)(n0 + ar) * ldb + ac * 8;
    uint32_t sAaddr = smB + ar * 80 + ac * 16;
    uint32_t sBaddr = smB + 10240 + ar * 80 + ac * 16;

    uint32_t aBase = smB + (wm + (lane & 15)) * 80 + ((lane >> 4) & 1) * 16;
    uint32_t bBase = smB + 10240 +
                     (wn + (lane & 7) + ((lane >> 4) & 1) * 8) * 80 +
                     ((lane >> 3) & 1) * 16;

    float acc[4][4][4];
#pragma unroll
    for (int i = 0; i < 4; i++)
#pragma unroll
        for (int j = 0; j < 4; j++)
#pragma unroll
            for (int v = 0; v < 4; v++) acc[i][j][v] = 0.f;

    // prologue: stage 0
    cp16(sAaddr, gA); cp16(sAaddr + 16, gA + 8);
    cp16(sBaddr, gB); cp16(sBaddr + 16, gB + 8);
    CP_COMMIT(); CP_WAIT0(); __syncthreads();

    int st = 0;
    for (int k0 = 0; k0 < K; k0 += 32) {
        bool more = (k0 + 32) < K;
        if (more) {
            int ns = st ^ 1;
            uint32_t d = sAaddr + ns * 20480;
            cp16(d, gA + k0 + 32); cp16(d + 16, gA + k0 + 40);
            uint32_t e = sBaddr + ns * 20480;
            cp16(e, gB + k0 + 32); cp16(e + 16, gB + k0 + 40);
            CP_COMMIT();
        }
        uint32_t sa = aBase + st * 20480;
        uint32_t sb = bBase + st * 20480;
#pragma unroll
        for (int kk = 0; kk < 2; kk++) {
            uint32_t af[4][4], bf[4][2];
#pragma unroll
            for (int i = 0; i < 4; i++)
                ldsm4(af[i][0], af[i][1], af[i][2], af[i][3],
                      sa + i * 1280 + kk * 32);
#pragma unroll
            for (int jp = 0; jp < 2; jp++)
                ldsm4(bf[2 * jp][0], bf[2 * jp][1], bf[2 * jp + 1][0],
                      bf[2 * jp + 1][1], sb + jp * 1280 + kk * 32);
#pragma unroll
            for (int i = 0; i < 4; i++)
#pragma unroll
                for (int j = 0; j < 4; j++)
                    mma_f16(acc[i][j], af[i][0], af[i][1], af[i][2], af[i][3],
                            bf[j][0], bf[j][1]);
        }
        if (more) { CP_WAIT0(); __syncthreads(); st ^= 1; }
    }

#pragma unroll
    for (int i = 0; i < 4; i++) {
        int row = m0 + wm + i * 16 + lr;
#pragma unroll
        for (int j = 0; j < 4; j++) {
            int col = n0 + wn + j * 8 + lc * 2;
            *(float2*)&C[(size_t)row * ldc + col] =
                make_float2(acc[i][j][0] * alpha, acc[i][j][1] * alpha);
            *(float2*)&C[(size_t)(row + 8) * ldc + col] =
                make_float2(acc[i][j][2] * alpha, acc[i][j][3] * alpha);
        }
    }
}

// ---------------- fp32 split-K GEMM (small), atomic accumulate ----------------
__device__ __forceinline__
void sg_body(const float* __restrict__ A, int lda,
             const float* __restrict__ B, int ldb,
             float* __restrict__ C, int ldc, int n0, int Ks) {
    __shared__ float As[8][64], Bs[8][64];
    int t = threadIdx.x;
    int row = t & 63, kc = t >> 6;
    int ty = t >> 4, tx = t & 15;
    float acc[4][4];
#pragma unroll
    for (int i = 0; i < 4; i++)
#pragma unroll
        for (int j = 0; j < 4; j++) acc[i][j] = 0.f;
    for (int k0 = 0; k0 < Ks; k0 += 8) {
        float2 a = *(const float2*)&A[(size_t)row * lda + k0 + kc * 2];
        float2 b = *(const float2*)&B[(size_t)(n0 + row) * ldb + k0 + kc * 2];
        As[kc * 2][row] = a.x; As[kc * 2 + 1][row] = a.y;
        Bs[kc * 2][row] = b.x; Bs[kc * 2 + 1][row] = b.y;
        __syncthreads();
#pragma unroll
        for (int k = 0; k < 8; k++) {
            float av[4] = {As[k][ty * 4], As[k][ty * 4 + 1],
                           As[k][ty * 4 + 2], As[k][ty * 4 + 3]};
            float bv[4] = {Bs[k][tx * 4], Bs[k][tx * 4 + 1],
                           Bs[k][tx * 4 + 2], Bs[k][tx * 4 + 3]};
#pragma unroll
            for (int i = 0; i < 4; i++)
#pragma unroll
                for (int j = 0; j < 4; j++)
                    acc[i][j] = fmaf(av[i], bv[j], acc[i][j]);
        }
        __syncthreads();
    }
#pragma unroll
    for (int i = 0; i < 4; i++)
#pragma unroll
        for (int j = 0; j < 4; j++)
            atomicAdd(&C[(size_t)(ty * 4 + i) * ldc + n0 + tx * 4 + j], acc[i][j]);
}

__global__ __launch_bounds__(256)
void sg_lin(const float* A, int lda, const float* B, int ldb,
            float* C, int ldc, int Ks) {
    sg_body(A + (size_t)blockIdx.y * 64 * lda + (size_t)blockIdx.z * Ks, lda,
            B + (size_t)blockIdx.z * Ks, ldb,
            C + (size_t)blockIdx.y * 64 * ldc, ldc, blockIdx.x * 64, Ks);
}
__global__ __launch_bounds__(256)
void sg_qk(const float* qp, const float* WkT, float* qk) {
    int h = blockIdx.z;
    sg_body(qp + h * 128, EDIM, WkT + h * 128, EDIM,
            qk + (size_t)h * 64 * EDIM, EDIM, blockIdx.x * 64, 128);
}
__global__ __launch_bounds__(256)
void sg_vproj(const float* U, const float* Wv, float* ctx) {
    int z = blockIdx.z;
    int bh = z >> 2, s = z & 3;
    int b = bh >> 5, h = bh & 31;
    sg_body(U + (size_t)bh * 64 * EDIM + s * 1024, EDIM,
            Wv + (size_t)h * 128 * EDIM + s * 1024, EDIM,
            ctx + (size_t)b * 64 * EDIM + h * 128, EDIM, blockIdx.x * 64, 1024);
}

__global__ void init_rows(float* C, const float* bias, int ld) {
    int f = blockIdx.x * 256 + threadIdx.x;
    C[(size_t)blockIdx.y * ld + f] = bias ? bias[f] : 0.f;
}

// ---------------- rope table build (one-time) ----------------
__global__ void build_rope_tab(float* __restrict__ tc, float* __restrict__ ts) {
    int idx = blockIdx.x * 256 + threadIdx.x;
    if (idx >= TAB_N) return;
    float theta;
    if (idx < 4096) {
        int t = idx >> 9, i = idx & 511;
        float pos = (float)t * (10.0f / 3.0f);
        float lo = floorf(pos); if (lo > 23.f) lo = 23.f;
        float hi = ceilf(pos);  if (hi > 23.f) hi = 23.f;
        float wgt = pos - lo;
        float pt = lo * (1.f - wgt) + hi * wgt;
        int j = 2 * i;
        int k = j & 511;
        theta = pt * powf(10000.f, -(float)(2 * k) / 1024.f);
    } else if (idx < 28672) {
        int r = idx - 4096;
        int hh = r / 768, ii = r % 768;
        int j = 2 * (ii + 512);
        int k = (j - 1024) % 768;
        theta = (float)hh * powf(10000.f, -(float)(2 * k) / 1536.f);
    } else {
        int r = idx - 28672;
        int ww = r / 768, ii = r % 768;
        int j = 2 * (ii + 1280);
        int k = (j - 2560) % 768;
        theta = (float)ww * powf(10000.f, -(float)(2 * k) / 1536.f);
    }
    tc[idx] = cosf(theta);
    ts[idx] = sinf(theta);
}

// ---------------- elementwise / misc ----------------
__global__ void cvt_h(const float* __restrict__ in, __half* __restrict__ out, int n4) {
    int i = blockIdx.x * blockDim.x + threadIdx.x;
    if (i < n4) {
        float4 v = ((const float4*)in)[i];
        ((__half2*)out)[i * 2]     = __floats2half2_rn(v.x, v.y);
        ((__half2*)out)[i * 2 + 1] = __floats2half2_rn(v.z, v.w);
    }
}

__global__ void transpose_hh(const __half* __restrict__ in, __half* __restrict__ out,
                             int R, int Cc, size_t sIn, size_t sOut) {
    __shared__ __half tile[32][33];
    in += (size_t)blockIdx.z * sIn;
    out += (size_t)blockIdx.z * sOut;
    int r0 = blockIdx.x * 32, c0 = blockIdx.y * 32;
    int x = threadIdx.x, y = threadIdx.y;
    for (int i = y; i < 32; i += 8)
        tile[i][x] = in[(size_t)(r0 + i) * Cc + c0 + x];
    __syncthreads();
    for (int i = y; i < 32; i += 8)
        out[(size_t)(c0 + i) * R + r0 + x] = tile[x][i];
}

__global__ void transpose_ff(const float* __restrict__ in, float* __restrict__ out, int N) {
    __shared__ float tile[32][33];
    int r0 = blockIdx.x * 32, c0 = blockIdx.y * 32;
    int x = threadIdx.x, y = threadIdx.y;
    for (int i = y; i < 32; i += 8)
        tile[i][x] = in[(size_t)(r0 + i) * N + c0 + x];
    __syncthreads();
    for (int i = y; i < 32; i += 8)
        out[(size_t)(c0 + i) * N + r0 + x] = tile[x][i];
}

__global__ void ln_rope_kernel(const float* __restrict__ kvr,
                               __half* __restrict__ hkv, __half* __restrict__ hrot,
                               const float* __restrict__ w, const float* __restrict__ b,
                               const float* __restrict__ tc, const float* __restrict__ ts) {
    __shared__ __align__(16) float row[4096];
    __shared__ float red[256];
    int rix = blockIdx.x;
    int l = rix & (Lseq - 1);
    size_t base = (size_t)rix * 4096;
    int tid = threadIdx.x;
    float s = 0.f;
    for (int i = tid; i < 4096; i += 256) { float v = kvr[base + i]; row[i] = v; s += v; }
    red[tid] = s; __syncthreads();
    for (int off = 128; off > 0; off >>= 1) {
        if (tid < off) red[tid] += red[tid + off];
        __syncthreads();
    }
    float mean = red[0] * (1.f / 4096.f);
    __syncthreads();
    float vs = 0.f;
    for (int i = tid; i < 4096; i += 256) { float d = row[i] - mean; vs += d * d; }
    red[tid] = vs; __syncthreads();
    for (int off = 128; off > 0; off >>= 1) {
        if (tid < off) red[tid] += red[tid + off];
        __syncthreads();
    }
    float inv = rsqrtf(red[0] * (1.f / 4096.f) + 1e-6f);
    __syncthreads();

    int tt = l >> 10;
    int rem = l & 1023;
    int hh = rem >> 5;
    int ww = rem & 31;
    int baseT = tt * 512;
    int baseH = 4096 + hh * 768 - 512;
    int baseW = 28672 + ww * 768 - 1280;

    for (int i = tid; i < 2048; i += 256) {
        int j = 2 * i;
        float x1 = (row[j] - mean) * inv * w[j] + b[j];
        float x2 = (row[j + 1] - mean) * inv * w[j + 1] + b[j + 1];
        int o = (i < 512) ? (baseT + i) : (i < 1280) ? (baseH + i) : (baseW + i);
        float cc = tc[o], ss = ts[o];
        *(__half2*)&hkv[base + j]  = __floats2half2_rn(x1, x2);
        *(__half2*)&hrot[base + j] = __floats2half2_rn(x1 * cc - x2 * ss,
                                                       x1 * ss + x2 * cc);
    }
}

__global__ void ln_kernel(const float* __restrict__ in, float* __restrict__ out,
                          const float* __restrict__ w, const float* __restrict__ b) {
    __shared__ __align__(16) float row[4096];
    __shared__ float red[256];
    size_t base = (size_t)blockIdx.x * 4096;
    int tid = threadIdx.x;
    float s = 0.f;
    for (int i = tid; i < 4096; i += 256) { float v = in[base + i]; row[i] = v; s += v; }
    red[tid] = s; __syncthreads();
    for (int off = 128; off > 0; off >>= 1) {
        if (tid < off) red[tid] += red[tid + off];
        __syncthreads();
    }
    float mean = red[0] * (1.f / 4096.f);
    __syncthreads();
    float vs = 0.f;
    for (int i = tid; i < 4096; i += 256) { float d = row[i] - mean; vs += d * d; }
    red[tid] = vs; __syncthreads();
    for (int off = 128; off > 0; off >>= 1) {
        if (tid < off) red[tid] += red[tid + off];
        __syncthreads();
    }
    float inv = rsqrtf(red[0] * (1.f / 4096.f) + 1e-6f);
    for (int i = tid; i < 4096; i += 256)
        out[base + i] = (row[i] - mean) * inv * w[i] + b[i];
}

__global__ void softmax_h(const float* __restrict__ s, __half* __restrict__ o) {
    __shared__ __align__(16) float rowc[Lseq];
    __shared__ float red[256];
    const float* p = s + (size_t)blockIdx.x * Lseq;
    __half* q = o + (size_t)blockIdx.x * Lseq;
    int tid = threadIdx.x;
    float mx = -1e30f;
    for (int i = tid; i < Lseq; i += 256) { float v = p[i]; rowc[i] = v; mx = fmaxf(mx, v); }
    red[tid] = mx; __syncthreads();
    for (int off = 128; off > 0; off >>= 1) {
        if (tid < off) red[tid] = fmaxf(red[tid], red[tid + off]);
        __syncthreads();
    }
    mx = red[0];
    __syncthreads();
    float sum = 0.f;
    for (int i = tid; i < Lseq; i += 256) {
        float e = expf(rowc[i] - mx);
        rowc[i] = e;
        sum += e;
    }
    red[tid] = sum; __syncthreads();
    for (int off = 128; off > 0; off >>= 1) {
        if (tid < off) red[tid] += red[tid + off];
        __syncthreads();
    }
    float inv = 1.f / red[0];
    __syncthreads();
    for (int i = tid; i < Lseq; i += 256) q[i] = (__half)(rowc[i] * inv);
}

__global__ void bias_combine(const float* __restrict__ Wout, const float* __restrict__ bv,
                             const float* __restrict__ bout, float* __restrict__ bc) {
    __shared__ float red[128];
    int f = blockIdx.x;
    int tid = threadIdx.x;
    float s = 0.f;
    for (int e = tid; e < EDIM; e += 128) s += Wout[(size_t)f * EDIM + e] * bv[e];
    red[tid] = s; __syncthreads();
    for (int off = 64; off > 0; off >>= 1) {
        if (tid < off) red[tid] += red[tid + off];
        __syncthreads();
    }
    if (tid == 0) bc[f] = red[0] + bout[f];
}

// ---------------- launch ----------------
extern "C" void kernel_launch(void* const* d_in, const int* in_sizes, int n_in,
                              void* d_out, int out_size) {
    const float* cube      = (const float*)d_in[0];
    const float* query     = (const float*)d_in[1];
    const float* kv_proj_w = (const float*)d_in[2];
    const float* ln_q_w    = (const float*)d_in[3];
    const float* ln_q_b    = (const float*)d_in[4];
    const float* ln_kv_w   = (const float*)d_in[5];
    const float* ln_kv_b   = (const float*)d_in[6];
    const float* ln_post_w = (const float*)d_in[7];
    const float* ln_post_b = (const float*)d_in[8];
    const float* in_proj_w = (const float*)d_in[9];
    const float* in_proj_b = (const float*)d_in[10];
    const float* out_proj_w= (const float*)d_in[11];
    const float* out_proj_b= (const float*)d_in[12];
    const float* proj      = (const float*)d_in[13];
    float* out = (float*)d_out;

    float *kvraw, *scores, *qn, *qp, *qk, *U, *ctx, *out1, *ln2, *WkT, *projT, *bc;
    float *tabc, *tabs;
    __half *hcube, *hw, *hkv, *hrot, *hkvT, *hattn, *hqk;
    cudaGetSymbolAddress((void**)&kvraw, g_kvraw);
    cudaGetSymbolAddress((void**)&hcube, g_hcube);
    cudaGetSymbolAddress((void**)&hw,    g_hw);
    cudaGetSymbolAddress((void**)&hkv,   g_hkv);
    cudaGetSymbolAddress((void**)&hrot,  g_hrot);
    cudaGetSymbolAddress((void**)&hkvT,  g_hkvT);
    cudaGetSymbolAddress((void**)&scores,g_scores);
    cudaGetSymbolAddress((void**)&hattn, g_hattn);
    cudaGetSymbolAddress((void**)&qn,    g_qn);
    cudaGetSymbolAddress((void**)&qp,    g_qp);
    cudaGetSymbolAddress((void**)&qk,    g_qk);
    cudaGetSymbolAddress((void**)&hqk,   g_hqk);
    cudaGetSymbolAddress((void**)&U,     g_U);
    cudaGetSymbolAddress((void**)&ctx,   g_ctx);
    cudaGetSymbolAddress((void**)&out1,  g_out1);
    cudaGetSymbolAddress((void**)&ln2,   g_ln2);
    cudaGetSymbolAddress((void**)&WkT,   g_WkT);
    cudaGetSymbolAddress((void**)&projT, g_projT);
    cudaGetSymbolAddress((void**)&bc,    g_bc);
    cudaGetSymbolAddress((void**)&tabc,  g_tabc);
    cudaGetSymbolAddress((void**)&tabs,  g_tabs);

    cudaFuncSetAttribute(gemm_h, cudaFuncAttributeMaxDynamicSharedMemorySize, GSMB);

    const size_t EE = (size_t)EDIM * EDIM;
    const float isq = 0.08838834764831845f;

    // conversions / prep
    build_rope_tab<<<(TAB_N + 255) / 256, 256>>>(tabc, tabs);
    cvt_h<<<(NROWS * VD / 4 + 255) / 256, 256>>>(cube, hcube, NROWS * VD / 4);
    cvt_h<<<(EDIM * VD / 4 + 255) / 256, 256>>>(kv_proj_w, hw, EDIM * VD / 4);
    transpose_ff<<<dim3(EDIM / 32, EDIM / 32), dim3(32, 8)>>>(in_proj_w + EE, WkT, EDIM);
    transpose_ff<<<dim3(EDIM / 32, EDIM / 32), dim3(32, 8)>>>(proj, projT, EDIM);
    bias_combine<<<EDIM, 128>>>(out_proj_w, in_proj_b + 2 * EDIM, out_proj_b, bc);

    // 1) kvraw = cube @ kv_proj_w^T (fp16 MMA, fp32 out)
    gemm_h<<<dim3(EDIM / 128, NROWS / 128, 1), 256, GSMB>>>(
        hcube, VD, 0, hw, VD, 0, kvraw, EDIM, 0, VD, 1.f);
    // 2) LN + RoPE -> hkv, hrot (table-driven)
    ln_rope_kernel<<<NROWS, 256>>>(kvraw, hkv, hrot, ln_kv_w, ln_kv_b, tabc, tabs);
    // 3) hkvT
    transpose_hh<<<dim3(Lseq / 32, EDIM / 32, Bb), dim3(32, 8)>>>(
        hkv, hkvT, Lseq, EDIM, (size_t)Lseq * EDIM, (size_t)EDIM * Lseq);

    // 4) q path (fp32)
    ln_kernel<<<NQ, 256>>>(query, qn, ln_q_w, ln_q_b);
    init_rows<<<dim3(EDIM / 256, NQ), 256>>>(qp, in_proj_b, EDIM);
    sg_lin<<<dim3(EDIM / 64, 1, 8), 256>>>(qn, EDIM, in_proj_w, EDIM, qp, EDIM, 512);
    // 5) qk (fp32 per head) -> fp16
    init_rows<<<dim3(EDIM / 256, 2048), 256>>>(qk, nullptr, EDIM);
    sg_qk<<<dim3(EDIM / 64, 1, NH), 256>>>(qp, WkT, qk);
    cvt_h<<<(2048 * EDIM / 4 + 255) / 256, 256>>>(qk, hqk, 2048 * EDIM / 4);

    // 6) scores = hqk @ hrot_b^T * isq
    gemm_h<<<dim3(Lseq / 128, 2048 / 128, Bb), 256, GSMB>>>(
        hqk, EDIM, 0, hrot, EDIM, (size_t)Lseq * EDIM,
        scores, Lseq, (size_t)2048 * Lseq, EDIM, isq);
    // 7) softmax -> fp16
    softmax_h<<<Bb * 2048, 256>>>(scores, hattn);
    // 8) U = attn @ kvT^T (fp32 out)
    gemm_h<<<dim3(EDIM / 128, 2048 / 128, Bb), 256, GSMB>>>(
        hattn, Lseq, (size_t)2048 * Lseq, hkvT, Lseq, (size_t)EDIM * Lseq,
        U, EDIM, (size_t)2048 * EDIM, Lseq, 1.f);

    // 9) ctx = U @ Wv_h^T (fp32)
    init_rows<<<dim3(EDIM / 256, 128), 256>>>(ctx, nullptr, EDIM);
    sg_vproj<<<dim3(2, 1, Bb * NH * 4), 256>>>(U, in_proj_w + 2 * EE, ctx);
    // 10) out1 = ctx @ Wout^T + bc
    init_rows<<<dim3(EDIM / 256, 128), 256>>>(out1, bc, EDIM);
    sg_lin<<<dim3(EDIM / 64, 2, 8), 256>>>(ctx, EDIM, out_proj_w, EDIM, out1, EDIM, 512);
    // 11) post-LN
    ln_kernel<<<128, 256>>>(out1, ln2, ln_post_w, ln_post_b);
    // 12) out = ln2 @ projT^T
    init_rows<<<dim3(EDIM / 256, 128), 256>>>(out, nullptr, EDIM);
    sg_lin<<<dim3(EDIM / 64, 2, 8), 256>>>(ln2, EDIM, projT, EDIM, out, EDIM, 512);
}